// round 8
// baseline (speedup 1.0000x reference)
#include <cuda_runtime.h>
#include <cstdint>

// ---------------------------------------------------------------------------
// PointGiraffeLayer: 3-NN interpolate -> FC(BN,ReLU) -> 3-NN interpolate -> FC
// B=2, N1=8192, N2=4096, N4=2048, C=128.
// GEMMs: mma.sync m16n8k8 tf32, 3xTF32 compensation, cp.async double buffer,
//        64x64 CTA tile for 3 CTAs/SM occupancy.
// ---------------------------------------------------------------------------

#define CCH 128

__device__ float g_f2i[2 * 4096 * CCH];
__device__ float g_h3 [2 * 4096 * CCH];
__device__ float g_n3 [2 * 4096 * CCH];
__device__ float g_n3i[2 * 8192 * CCH];
__device__ float g_h4 [2 * 8192 * CCH];
__device__ float g_psum[512 * 128];
__device__ float g_psq [512 * 128];
__device__ float g_scale[128];
__device__ float g_shift[128];

__device__ __forceinline__ uint32_t tf32_rna(float a) {
    uint32_t u;
    asm("cvt.rna.tf32.f32 %0, %1;" : "=r"(u) : "f"(a));
    return u;
}

__device__ __forceinline__ void mma_tf32(float c[4], const uint32_t a[4],
                                         const uint32_t b[2]) {
    asm volatile(
        "mma.sync.aligned.m16n8k8.row.col.f32.tf32.tf32.f32 "
        "{%0,%1,%2,%3}, {%4,%5,%6,%7}, {%8,%9}, {%0,%1,%2,%3};"
        : "+f"(c[0]), "+f"(c[1]), "+f"(c[2]), "+f"(c[3])
        : "r"(a[0]), "r"(a[1]), "r"(a[2]), "r"(a[3]), "r"(b[0]), "r"(b[1]));
}

__device__ __forceinline__ uint32_t smem_u32(const void* p) {
    uint32_t a;
    asm("{ .reg .u64 t; cvta.to.shared.u64 t, %1; cvt.u32.u64 %0, t; }"
        : "=r"(a) : "l"(p));
    return a;
}
__device__ __forceinline__ void cp_async16(uint32_t saddr, const void* g) {
    asm volatile("cp.async.ca.shared.global [%0], [%1], 16;" :: "r"(saddr), "l"(g));
}
__device__ __forceinline__ void cp_commit() {
    asm volatile("cp.async.commit_group;" ::: "memory");
}
template <int N>
__device__ __forceinline__ void cp_wait() {
    asm volatile("cp.async.wait_group %0;" :: "n"(N) : "memory");
}

// ---------------------------------------------------------------------------
// 3-NN interpolation. TPW=8 targets per warp.
// ---------------------------------------------------------------------------
__device__ __forceinline__ void ins3(float d, int s,
                                     float& d0, int& i0,
                                     float& d1, int& i1,
                                     float& d2, int& i2) {
    if (d < d2) {
        if (d < d1) {
            d2 = d1; i2 = i1;
            if (d < d0) { d1 = d0; i1 = i0; d0 = d; i0 = s; }
            else        { d1 = d;  i1 = s; }
        } else { d2 = d; i2 = s; }
    }
}

constexpr int IWARPS = 8;
constexpr int TPW    = 8;

__global__ void interp3nn(const float* __restrict__ src_xyz,
                          const float* __restrict__ tgt_xyz,
                          const float* __restrict__ feats,
                          float* __restrict__ out,
                          int NS, int NT) {
    extern __shared__ float4 sp[];

    const int b = blockIdx.y;
    const float* S = src_xyz + (size_t)b * NS * 3;
    for (int i = threadIdx.x; i < NS; i += blockDim.x) {
        float4 p;
        p.x = S[3 * i + 0];
        p.y = S[3 * i + 1];
        p.z = S[3 * i + 2];
        p.w = 0.f;
        sp[i] = p;
    }
    __syncthreads();

    const int warp = threadIdx.x >> 5;
    const int lane = threadIdx.x & 31;
    const int tbase = (blockIdx.x * IWARPS + warp) * TPW;
    if (tbase >= NT) return;

    float tx[TPW], ty[TPW], tz[TPW];
    float d0[TPW], d1[TPW], d2[TPW];
    int   i0[TPW], i1[TPW], i2[TPW];
#pragma unroll
    for (int j = 0; j < TPW; j++) {
        int t = min(tbase + j, NT - 1);
        const float* T = tgt_xyz + ((size_t)b * NT + t) * 3;
        tx[j] = T[0]; ty[j] = T[1]; tz[j] = T[2];
        d0[j] = d1[j] = d2[j] = 3.4e38f;
        i0[j] = i1[j] = i2[j] = 0;
    }

    for (int s = lane; s < NS; s += 32) {
        float4 p = sp[s];
#pragma unroll
        for (int j = 0; j < TPW; j++) {
            float dx = tx[j] - p.x, dy = ty[j] - p.y, dz = tz[j] - p.z;
            float d = dx * dx + dy * dy + dz * dz;
            ins3(d, s, d0[j], i0[j], d1[j], i1[j], d2[j], i2[j]);
        }
    }

#pragma unroll
    for (int j = 0; j < TPW; j++) {
#pragma unroll
        for (int off = 16; off > 0; off >>= 1) {
            float od0 = __shfl_xor_sync(0xffffffffu, d0[j], off);
            int   oi0 = __shfl_xor_sync(0xffffffffu, i0[j], off);
            float od1 = __shfl_xor_sync(0xffffffffu, d1[j], off);
            int   oi1 = __shfl_xor_sync(0xffffffffu, i1[j], off);
            float od2 = __shfl_xor_sync(0xffffffffu, d2[j], off);
            int   oi2 = __shfl_xor_sync(0xffffffffu, i2[j], off);
            ins3(od0, oi0, d0[j], i0[j], d1[j], i1[j], d2[j], i2[j]);
            ins3(od1, oi1, d0[j], i0[j], d1[j], i1[j], d2[j], i2[j]);
            ins3(od2, oi2, d0[j], i0[j], d1[j], i1[j], d2[j], i2[j]);
        }
    }

#pragma unroll
    for (int j = 0; j < TPW; j++) {
        int t = tbase + j;
        if (t >= NT) break;
        float s0 = sqrtf(fmaxf(d0[j], 0.f));
        float s1 = sqrtf(fmaxf(d1[j], 0.f));
        float s2 = sqrtf(fmaxf(d2[j], 0.f));
        float w0 = 1.f / (s0 + 1e-8f);
        float w1 = 1.f / (s1 + 1e-8f);
        float w2 = 1.f / (s2 + 1e-8f);
        float wi = 1.f / (w0 + w1 + w2);
        w0 *= wi; w1 *= wi; w2 *= wi;

        const float4* f0 = (const float4*)(feats + ((size_t)b * NS + i0[j]) * CCH);
        const float4* f1 = (const float4*)(feats + ((size_t)b * NS + i1[j]) * CCH);
        const float4* f2 = (const float4*)(feats + ((size_t)b * NS + i2[j]) * CCH);
        float4 a = f0[lane], bb = f1[lane], cc = f2[lane];
        float4 r;
        r.x = w0 * a.x + w1 * bb.x + w2 * cc.x;
        r.y = w0 * a.y + w1 * bb.y + w2 * cc.y;
        r.z = w0 * a.z + w1 * bb.z + w2 * cc.z;
        r.w = w0 * a.w + w1 * bb.w + w2 * cc.w;
        ((float4*)(out + ((size_t)b * NT + t) * CCH))[lane] = r;
    }
}

// ---------------------------------------------------------------------------
// mma.sync tf32 GEMM, cp.async double-buffered, register-side 3xTF32 split.
// C (rows x 128) = X (rows x KD) @ W^T.  CTA tile 64(M) x 64(N) x 32(K).
// 256 threads = 8 warps (4m x 2n), warp tile 16x32.  grid = (rows/64, 2).
// ---------------------------------------------------------------------------
constexpr int SA = 36;   // padded smem row stride (words)
constexpr int SC = 68;   // epilogue stage stride
constexpr int A_WORDS = 64 * SA;    // 2304
constexpr int B_WORDS = 64 * SA;    // 2304
constexpr int OFF_SCL = 0;          // scale[128], shift[128]
constexpr int OFF_A   = 256;
constexpr int OFF_B   = OFF_A + 2 * A_WORDS;
constexpr int GEMM_SMEM = (OFF_B + 2 * B_WORDS) * 4;   // 37888 B

template <int KD, bool SPLIT, bool AFFINE, bool SUMS, bool BIAS>
__global__ __launch_bounds__(256) void gemm_mma(
        const float* __restrict__ A0, const float* __restrict__ A1,
        const float* __restrict__ W,
        const float* __restrict__ scale, const float* __restrict__ shift,
        const float* __restrict__ bias,
        float* __restrict__ Cout,
        float* __restrict__ psum, float* __restrict__ psq) {
    extern __shared__ float smf[];
    const uint32_t smb = smem_u32(smf);

    const int t    = threadIdx.x;
    const int lane = t & 31;
    const int warp = t >> 5;
    const int wm   = warp >> 1;          // 0..3 -> 16 rows each
    const int wn   = warp & 1;           // 0..1 -> 32 cols each
    const int g    = lane >> 2;
    const int tig  = lane & 3;
    const int blockRow = blockIdx.x * 64;
    const int oc0      = blockIdx.y * 64;

    if (AFFINE) {
        if (t < 128) {
            smf[OFF_SCL + t]       = scale[t];
            smf[OFF_SCL + 128 + t] = shift[t];
        }
    }

    const int arow = t >> 3;            // 0..31
    const int acq  = (t & 7) * 4;

    auto prefetch = [&](int kc) {
        int buf = kc & 1;
        uint32_t abase = smb + (OFF_A + buf * A_WORDS) * 4;
#pragma unroll
        for (int i = 0; i < 2; i++) {
            int row = arow + i * 32;
            int kg  = kc * 32 + acq;
            const float* src;
            if (SPLIT) {
                src = (kg < 128) ? A0 + (size_t)(blockRow + row) * 128 + kg
                                 : A1 + (size_t)(blockRow + row) * 128 + (kg - 128);
            } else {
                src = A0 + (size_t)(blockRow + row) * KD + kg;
            }
            cp_async16(abase + (row * SA + acq) * 4, src);
        }
        uint32_t bbase = smb + (OFF_B + buf * B_WORDS) * 4;
#pragma unroll
        for (int i = 0; i < 2; i++) {
            int row = arow + i * 32;
            const float* src = W + (size_t)(oc0 + row) * KD + kc * 32 + acq;
            cp_async16(bbase + (row * SA + acq) * 4, src);
        }
        cp_commit();
    };

    float c[4][4];
#pragma unroll
    for (int bn = 0; bn < 4; bn++)
#pragma unroll
        for (int r = 0; r < 4; r++) c[bn][r] = 0.f;

    constexpr int CH = KD / 32;
    prefetch(0);

#pragma unroll
    for (int kc = 0; kc < CH; kc++) {
        __syncthreads();
        if (kc + 1 < CH) {
            prefetch(kc + 1);
            cp_wait<1>();
        } else {
            cp_wait<0>();
        }
        __syncthreads();

        const float* Ab = smf + OFF_A + (kc & 1) * A_WORDS;
        const float* Bb = smf + OFF_B + (kc & 1) * B_WORDS;

#pragma unroll
        for (int ks = 0; ks < 4; ks++) {
            const int k0 = ks * 8;
            float sc0 = 1.f, sh0 = 0.f, sc1 = 1.f, sh1 = 0.f;
            if (AFFINE) {
                int kg = kc * 32 + k0 + tig;
                sc0 = smf[OFF_SCL + kg];
                sh0 = smf[OFF_SCL + 128 + kg];
                sc1 = smf[OFF_SCL + kg + 4];
                sh1 = smf[OFF_SCL + 128 + kg + 4];
            }
            uint32_t ah[4], al[4];
            {
                int r = wm * 16 + g;
                float v0 = Ab[(r    ) * SA + k0 + tig];
                float v1 = Ab[(r + 8) * SA + k0 + tig];
                float v2 = Ab[(r    ) * SA + k0 + tig + 4];
                float v3 = Ab[(r + 8) * SA + k0 + tig + 4];
                if (AFFINE) {
                    v0 = fmaxf(v0 * sc0 + sh0, 0.f);
                    v1 = fmaxf(v1 * sc0 + sh0, 0.f);
                    v2 = fmaxf(v2 * sc1 + sh1, 0.f);
                    v3 = fmaxf(v3 * sc1 + sh1, 0.f);
                }
                ah[0] = tf32_rna(v0); al[0] = __float_as_uint(v0 - __uint_as_float(ah[0]));
                ah[1] = tf32_rna(v1); al[1] = __float_as_uint(v1 - __uint_as_float(ah[1]));
                ah[2] = tf32_rna(v2); al[2] = __float_as_uint(v2 - __uint_as_float(ah[2]));
                ah[3] = tf32_rna(v3); al[3] = __float_as_uint(v3 - __uint_as_float(ah[3]));
            }
            uint32_t bh[4][2], bl[4][2];
#pragma unroll
            for (int bn = 0; bn < 4; bn++) {
                int n = wn * 32 + bn * 8 + g;
                float w0 = Bb[n * SA + k0 + tig];
                float w1 = Bb[n * SA + k0 + tig + 4];
                bh[bn][0] = tf32_rna(w0); bl[bn][0] = __float_as_uint(w0 - __uint_as_float(bh[bn][0]));
                bh[bn][1] = tf32_rna(w1); bl[bn][1] = __float_as_uint(w1 - __uint_as_float(bh[bn][1]));
            }
#pragma unroll
            for (int bn = 0; bn < 4; bn++) {
                mma_tf32(c[bn], ah, bh[bn]);
                mma_tf32(c[bn], ah, bl[bn]);
                mma_tf32(c[bn], al, bh[bn]);
            }
        }
    }

    // ---- epilogue: frags -> smem stage (pre-bias) ----
    __syncthreads();
    float* stage = smf;
    {
        int row0 = wm * 16 + g;
#pragma unroll
        for (int bn = 0; bn < 4; bn++) {
            int col = wn * 32 + bn * 8 + 2 * tig;
            stage[(row0    ) * SC + col    ] = c[bn][0];
            stage[(row0    ) * SC + col + 1] = c[bn][1];
            stage[(row0 + 8) * SC + col    ] = c[bn][2];
            stage[(row0 + 8) * SC + col + 1] = c[bn][3];
        }
    }
    __syncthreads();

    if (SUMS && t < 64) {
        float s = 0.f, q = 0.f;
#pragma unroll 8
        for (int r = 0; r < 64; r++) {
            float v = stage[r * SC + t];
            s += v; q += v * v;
        }
        psum[blockIdx.x * 128 + oc0 + t] = s;
        psq [blockIdx.x * 128 + oc0 + t] = q;
    }

    // coalesced store: 64 rows x 16 float4 = 1024 slots, 4 per thread
#pragma unroll
    for (int i = 0; i < 4; i++) {
        int idx = t + i * 256;
        int row = idx >> 4;
        int cq  = (idx & 15) * 4;
        float4 v = *(float4*)&stage[row * SC + cq];
        if (BIAS) {
            v.x += bias[oc0 + cq + 0];
            v.y += bias[oc0 + cq + 1];
            v.z += bias[oc0 + cq + 2];
            v.w += bias[oc0 + cq + 3];
        }
        *(float4*)(Cout + (size_t)(blockRow + row) * 128 + oc0 + cq) = v;
    }
}

// ---------------------------------------------------------------------------
// BN finalize (parallel)
// ---------------------------------------------------------------------------
__global__ __launch_bounds__(1024) void bn_finalize(
        const float* __restrict__ psum, const float* __restrict__ psq,
        int nchunks, float invN,
        const float* __restrict__ g, const float* __restrict__ b,
        float* __restrict__ scale, float* __restrict__ shift) {
    __shared__ float ssum[8][128];
    __shared__ float ssq [8][128];
    const int c     = threadIdx.x & 127;
    const int slice = threadIdx.x >> 7;

    float s = 0.f, q = 0.f;
    for (int k = slice; k < nchunks; k += 8) {
        s += psum[k * 128 + c];
        q += psq [k * 128 + c];
    }
    ssum[slice][c] = s;
    ssq [slice][c] = q;
    __syncthreads();

    if (threadIdx.x < 128) {
        float ts = 0.f, tq = 0.f;
#pragma unroll
        for (int y = 0; y < 8; y++) { ts += ssum[y][c]; tq += ssq[y][c]; }
        float mu  = ts * invN;
        float var = fmaxf(tq * invN - mu * mu, 0.f);
        float sc  = g[c] * rsqrtf(var + 1e-5f);
        scale[c] = sc;
        shift[c] = b[c] - mu * sc;
    }
}

// ---------------------------------------------------------------------------
// Launch
// ---------------------------------------------------------------------------
extern "C" void kernel_launch(void* const* d_in, const int* in_sizes, int n_in,
                              void* d_out, int out_size) {
    const float* pts_r1 = (const float*)d_in[0];
    const float* pts_r2 = (const float*)d_in[1];
    const float* pts_r4 = (const float*)d_in[2];
    const float* feat0  = (const float*)d_in[3];
    const float* feat1  = (const float*)d_in[4];
    const float* feat2  = (const float*)d_in[5];
    const float* w3a = (const float*)d_in[6];
    const float* g3  = (const float*)d_in[7];
    const float* b3  = (const float*)d_in[8];
    const float* w3b = (const float*)d_in[9];
    const float* bb3 = (const float*)d_in[10];
    const float* w4a = (const float*)d_in[11];
    const float* g4  = (const float*)d_in[12];
    const float* b4  = (const float*)d_in[13];
    const float* w4b = (const float*)d_in[14];
    const float* bb4 = (const float*)d_in[15];

    const int B  = 2;
    const int N1 = in_sizes[0] / (3 * B);   // 8192
    const int N2 = in_sizes[1] / (3 * B);   // 4096
    const int N4 = in_sizes[2] / (3 * B);   // 2048

    float *f2i, *h3, *n3, *n3i, *h4, *psum, *psq, *scale, *shift;
    cudaGetSymbolAddress((void**)&f2i,   g_f2i);
    cudaGetSymbolAddress((void**)&h3,    g_h3);
    cudaGetSymbolAddress((void**)&n3,    g_n3);
    cudaGetSymbolAddress((void**)&n3i,   g_n3i);
    cudaGetSymbolAddress((void**)&h4,    g_h4);
    cudaGetSymbolAddress((void**)&psum,  g_psum);
    cudaGetSymbolAddress((void**)&psq,   g_psq);
    cudaGetSymbolAddress((void**)&scale, g_scale);
    cudaGetSymbolAddress((void**)&shift, g_shift);

    cudaFuncSetAttribute(interp3nn, cudaFuncAttributeMaxDynamicSharedMemorySize,
                         (int)(4096 * sizeof(float4)));

    // --- fnode 3: interp feat2 (r4 grid) onto r2 grid ---
    {
        dim3 grid((N2 + IWARPS * TPW - 1) / (IWARPS * TPW), B);
        size_t shmem = (size_t)N4 * sizeof(float4);
        interp3nn<<<grid, 256, shmem>>>(pts_r4, pts_r2, feat2, f2i, N4, N2);
    }
    gemm_mma<256, true, false, true, false>
        <<<dim3((B * N2) / 64, 2), 256, GEMM_SMEM>>>(
        feat1, f2i, w3a, nullptr, nullptr, nullptr, h3, psum, psq);
    bn_finalize<<<1, 1024>>>(psum, psq, (B * N2) / 64, 1.f / (B * N2), g3, b3, scale, shift);
    gemm_mma<128, false, true, false, true>
        <<<dim3((B * N2) / 64, 2), 256, GEMM_SMEM>>>(
        h3, nullptr, w3b, scale, shift, bb3, n3, nullptr, nullptr);

    // --- fnode 4: interp n3 (r2 grid) onto r1 grid ---
    {
        dim3 grid((N1 + IWARPS * TPW - 1) / (IWARPS * TPW), B);
        size_t shmem = (size_t)N2 * sizeof(float4);
        interp3nn<<<grid, 256, shmem>>>(pts_r2, pts_r1, n3, n3i, N2, N1);
    }
    gemm_mma<256, true, false, true, false>
        <<<dim3((B * N1) / 64, 2), 256, GEMM_SMEM>>>(
        feat0, n3i, w4a, nullptr, nullptr, nullptr, h4, psum, psq);
    bn_finalize<<<1, 1024>>>(psum, psq, (B * N1) / 64, 1.f / (B * N1), g4, b4, scale, shift);
    gemm_mma<128, false, true, false, true>
        <<<dim3((B * N1) / 64, 2), 256, GEMM_SMEM>>>(
        h4, nullptr, w4b, scale, shift, bb4, (float*)d_out, nullptr, nullptr);
}

// round 11
// speedup vs baseline: 1.0562x; 1.0562x over previous
#include <cuda_runtime.h>
#include <cstdint>

// ---------------------------------------------------------------------------
// PointGiraffeLayer: 3-NN interpolate -> FC(BN,ReLU) -> 3-NN interpolate -> FC
// B=2, N1=8192, N2=4096, N4=2048, C=128.
// GEMMs: mma.sync m16n8k8 tf32, 3xTF32 compensation, cp.async double buffer.
// BM=64 tiles for 8192-row GEMMs (SM coverage), BM=128 for 16384-row GEMMs.
// Interp: numerically-stable explicit (t-s) distances (NN selection must not
// use the |s|^2-2ts expansion -- cancellation flips neighbor selection).
// ---------------------------------------------------------------------------

#define CCH 128

__device__ float g_f2i[2 * 4096 * CCH];
__device__ float g_h3 [2 * 4096 * CCH];
__device__ float g_n3 [2 * 4096 * CCH];
__device__ float g_n3i[2 * 8192 * CCH];
__device__ float g_h4 [2 * 8192 * CCH];
__device__ float g_psum[512 * 128];
__device__ float g_psq [512 * 128];
__device__ float g_scale[128];
__device__ float g_shift[128];

__device__ __forceinline__ uint32_t tf32_rna(float a) {
    uint32_t u;
    asm("cvt.rna.tf32.f32 %0, %1;" : "=r"(u) : "f"(a));
    return u;
}

__device__ __forceinline__ void mma_tf32(float c[4], const uint32_t a[4],
                                         const uint32_t b[2]) {
    asm volatile(
        "mma.sync.aligned.m16n8k8.row.col.f32.tf32.tf32.f32 "
        "{%0,%1,%2,%3}, {%4,%5,%6,%7}, {%8,%9}, {%0,%1,%2,%3};"
        : "+f"(c[0]), "+f"(c[1]), "+f"(c[2]), "+f"(c[3])
        : "r"(a[0]), "r"(a[1]), "r"(a[2]), "r"(a[3]), "r"(b[0]), "r"(b[1]));
}

__device__ __forceinline__ uint32_t smem_u32(const void* p) {
    uint32_t a;
    asm("{ .reg .u64 t; cvta.to.shared.u64 t, %1; cvt.u32.u64 %0, t; }"
        : "=r"(a) : "l"(p));
    return a;
}
__device__ __forceinline__ void cp_async16(uint32_t saddr, const void* g) {
    asm volatile("cp.async.ca.shared.global [%0], [%1], 16;" :: "r"(saddr), "l"(g));
}
__device__ __forceinline__ void cp_commit() {
    asm volatile("cp.async.commit_group;" ::: "memory");
}
template <int N>
__device__ __forceinline__ void cp_wait() {
    asm volatile("cp.async.wait_group %0;" :: "n"(N) : "memory");
}

// ---------------------------------------------------------------------------
// 3-NN interpolation. TPW=4 targets per warp; explicit (t-s) distances.
// ---------------------------------------------------------------------------
__device__ __forceinline__ void ins3(float d, int s,
                                     float& d0, int& i0,
                                     float& d1, int& i1,
                                     float& d2, int& i2) {
    if (d < d2) {
        if (d < d1) {
            d2 = d1; i2 = i1;
            if (d < d0) { d1 = d0; i1 = i0; d0 = d; i0 = s; }
            else        { d1 = d;  i1 = s; }
        } else { d2 = d; i2 = s; }
    }
}

constexpr int IWARPS = 8;
constexpr int TPW    = 4;

__global__ void interp3nn(const float* __restrict__ src_xyz,
                          const float* __restrict__ tgt_xyz,
                          const float* __restrict__ feats,
                          float* __restrict__ out,
                          int NS, int NT) {
    extern __shared__ float4 sp[];

    const int b = blockIdx.y;
    const float* S = src_xyz + (size_t)b * NS * 3;
    for (int i = threadIdx.x; i < NS; i += blockDim.x) {
        float4 p;
        p.x = S[3 * i + 0];
        p.y = S[3 * i + 1];
        p.z = S[3 * i + 2];
        p.w = 0.f;
        sp[i] = p;
    }
    __syncthreads();

    const int warp = threadIdx.x >> 5;
    const int lane = threadIdx.x & 31;
    const int tbase = (blockIdx.x * IWARPS + warp) * TPW;
    if (tbase >= NT) return;

    float tx[TPW], ty[TPW], tz[TPW];
    float d0[TPW], d1[TPW], d2[TPW];
    int   i0[TPW], i1[TPW], i2[TPW];
#pragma unroll
    for (int j = 0; j < TPW; j++) {
        int t = min(tbase + j, NT - 1);
        const float* T = tgt_xyz + ((size_t)b * NT + t) * 3;
        tx[j] = T[0]; ty[j] = T[1]; tz[j] = T[2];
        d0[j] = d1[j] = d2[j] = 3.4e38f;
        i0[j] = i1[j] = i2[j] = 0;
    }

    for (int s = lane; s < NS; s += 32) {
        float4 p = sp[s];
#pragma unroll
        for (int j = 0; j < TPW; j++) {
            float dx = tx[j] - p.x, dy = ty[j] - p.y, dz = tz[j] - p.z;
            float d = dx * dx + dy * dy + dz * dz;
            ins3(d, s, d0[j], i0[j], d1[j], i1[j], d2[j], i2[j]);
        }
    }

#pragma unroll
    for (int j = 0; j < TPW; j++) {
#pragma unroll
        for (int off = 16; off > 0; off >>= 1) {
            float od0 = __shfl_xor_sync(0xffffffffu, d0[j], off);
            int   oi0 = __shfl_xor_sync(0xffffffffu, i0[j], off);
            float od1 = __shfl_xor_sync(0xffffffffu, d1[j], off);
            int   oi1 = __shfl_xor_sync(0xffffffffu, i1[j], off);
            float od2 = __shfl_xor_sync(0xffffffffu, d2[j], off);
            int   oi2 = __shfl_xor_sync(0xffffffffu, i2[j], off);
            ins3(od0, oi0, d0[j], i0[j], d1[j], i1[j], d2[j], i2[j]);
            ins3(od1, oi1, d0[j], i0[j], d1[j], i1[j], d2[j], i2[j]);
            ins3(od2, oi2, d0[j], i0[j], d1[j], i1[j], d2[j], i2[j]);
        }
    }

#pragma unroll
    for (int j = 0; j < TPW; j++) {
        int t = tbase + j;
        if (t >= NT) break;
        float s0 = sqrtf(fmaxf(d0[j], 0.f));
        float s1 = sqrtf(fmaxf(d1[j], 0.f));
        float s2 = sqrtf(fmaxf(d2[j], 0.f));
        float w0 = 1.f / (s0 + 1e-8f);
        float w1 = 1.f / (s1 + 1e-8f);
        float w2 = 1.f / (s2 + 1e-8f);
        float wi = 1.f / (w0 + w1 + w2);
        w0 *= wi; w1 *= wi; w2 *= wi;

        const float4* f0 = (const float4*)(feats + ((size_t)b * NS + i0[j]) * CCH);
        const float4* f1 = (const float4*)(feats + ((size_t)b * NS + i1[j]) * CCH);
        const float4* f2 = (const float4*)(feats + ((size_t)b * NS + i2[j]) * CCH);
        float4 a = f0[lane], bb = f1[lane], cc = f2[lane];
        float4 r;
        r.x = w0 * a.x + w1 * bb.x + w2 * cc.x;
        r.y = w0 * a.y + w1 * bb.y + w2 * cc.y;
        r.z = w0 * a.z + w1 * bb.z + w2 * cc.z;
        r.w = w0 * a.w + w1 * bb.w + w2 * cc.w;
        ((float4*)(out + ((size_t)b * NT + t) * CCH))[lane] = r;
    }
}

// ---------------------------------------------------------------------------
// mma.sync tf32 GEMM, cp.async double-buffered, register-side 3xTF32 split.
// C (rows x 128) = X (rows x KD) @ W^T.  CTA tile BM(M) x 64(N) x 32(K).
// 256 threads = 8 warps (4m x 2n); warp tile (BM/4) x 32. grid=(rows/BM, 2).
// ---------------------------------------------------------------------------
constexpr int SA = 36;   // padded smem row stride (words)
constexpr int SC = 68;   // epilogue stage stride
constexpr int OFF_SCL = 0;
constexpr int OFF_A   = 256;

template <int BM, int KD, bool SPLIT, bool AFFINE, bool SUMS, bool BIAS>
__global__ __launch_bounds__(256) void gemm_mma(
        const float* __restrict__ A0, const float* __restrict__ A1,
        const float* __restrict__ W,
        const float* __restrict__ scale, const float* __restrict__ shift,
        const float* __restrict__ bias,
        float* __restrict__ Cout,
        float* __restrict__ psum, float* __restrict__ psq) {
    constexpr int AM      = BM / 64;          // a-subtiles per warp (1 or 2)
    constexpr int A_WORDS = BM * SA;
    constexpr int B_WORDS = 64 * SA;
    constexpr int OFF_B   = OFF_A + 2 * A_WORDS;

    extern __shared__ float smf[];
    const uint32_t smb = smem_u32(smf);

    const int t    = threadIdx.x;
    const int lane = t & 31;
    const int warp = t >> 5;
    const int wm   = warp >> 1;
    const int wn   = warp & 1;
    const int g    = lane >> 2;
    const int tig  = lane & 3;
    const int blockRow = blockIdx.x * BM;
    const int oc0      = blockIdx.y * 64;

    if (AFFINE) {
        if (t < 128) {
            smf[OFF_SCL + t]       = scale[t];
            smf[OFF_SCL + 128 + t] = shift[t];
        }
    }

    const int arow = t >> 3;
    const int acq  = (t & 7) * 4;

    auto prefetch = [&](int kc) {
        int buf = kc & 1;
        uint32_t abase = smb + (OFF_A + buf * A_WORDS) * 4;
#pragma unroll
        for (int i = 0; i < BM / 32; i++) {
            int row = arow + i * 32;
            int kg  = kc * 32 + acq;
            const float* src;
            if (SPLIT) {
                src = (kg < 128) ? A0 + (size_t)(blockRow + row) * 128 + kg
                                 : A1 + (size_t)(blockRow + row) * 128 + (kg - 128);
            } else {
                src = A0 + (size_t)(blockRow + row) * KD + kg;
            }
            cp_async16(abase + (row * SA + acq) * 4, src);
        }
        uint32_t bbase = smb + (OFF_B + buf * B_WORDS) * 4;
#pragma unroll
        for (int i = 0; i < 2; i++) {
            int row = arow + i * 32;
            const float* src = W + (size_t)(oc0 + row) * KD + kc * 32 + acq;
            cp_async16(bbase + (row * SA + acq) * 4, src);
        }
        cp_commit();
    };

    float c[AM][4][4];
#pragma unroll
    for (int am = 0; am < AM; am++)
#pragma unroll
        for (int bn = 0; bn < 4; bn++)
#pragma unroll
            for (int r = 0; r < 4; r++) c[am][bn][r] = 0.f;

    constexpr int CH = KD / 32;
    prefetch(0);

#pragma unroll
    for (int kc = 0; kc < CH; kc++) {
        __syncthreads();
        if (kc + 1 < CH) {
            prefetch(kc + 1);
            cp_wait<1>();
        } else {
            cp_wait<0>();
        }
        __syncthreads();

        const float* Ab = smf + OFF_A + (kc & 1) * A_WORDS;
        const float* Bb = smf + OFF_B + (kc & 1) * B_WORDS;

#pragma unroll
        for (int ks = 0; ks < 4; ks++) {
            const int k0 = ks * 8;
            float sc0 = 1.f, sh0 = 0.f, sc1 = 1.f, sh1 = 0.f;
            if (AFFINE) {
                int kg = kc * 32 + k0 + tig;
                sc0 = smf[OFF_SCL + kg];
                sh0 = smf[OFF_SCL + 128 + kg];
                sc1 = smf[OFF_SCL + kg + 4];
                sh1 = smf[OFF_SCL + 128 + kg + 4];
            }
            uint32_t ah[AM][4], al[AM][4];
#pragma unroll
            for (int am = 0; am < AM; am++) {
                int r = wm * (BM / 4) + am * 16 + g;
                float v0 = Ab[(r    ) * SA + k0 + tig];
                float v1 = Ab[(r + 8) * SA + k0 + tig];
                float v2 = Ab[(r    ) * SA + k0 + tig + 4];
                float v3 = Ab[(r + 8) * SA + k0 + tig + 4];
                if (AFFINE) {
                    v0 = fmaxf(v0 * sc0 + sh0, 0.f);
                    v1 = fmaxf(v1 * sc0 + sh0, 0.f);
                    v2 = fmaxf(v2 * sc1 + sh1, 0.f);
                    v3 = fmaxf(v3 * sc1 + sh1, 0.f);
                }
                ah[am][0] = tf32_rna(v0); al[am][0] = __float_as_uint(v0 - __uint_as_float(ah[am][0]));
                ah[am][1] = tf32_rna(v1); al[am][1] = __float_as_uint(v1 - __uint_as_float(ah[am][1]));
                ah[am][2] = tf32_rna(v2); al[am][2] = __float_as_uint(v2 - __uint_as_float(ah[am][2]));
                ah[am][3] = tf32_rna(v3); al[am][3] = __float_as_uint(v3 - __uint_as_float(ah[am][3]));
            }
            uint32_t bh[4][2], bl[4][2];
#pragma unroll
            for (int bn = 0; bn < 4; bn++) {
                int n = wn * 32 + bn * 8 + g;
                float w0 = Bb[n * SA + k0 + tig];
                float w1 = Bb[n * SA + k0 + tig + 4];
                bh[bn][0] = tf32_rna(w0); bl[bn][0] = __float_as_uint(w0 - __uint_as_float(bh[bn][0]));
                bh[bn][1] = tf32_rna(w1); bl[bn][1] = __float_as_uint(w1 - __uint_as_float(bh[bn][1]));
            }
#pragma unroll
            for (int am = 0; am < AM; am++)
#pragma unroll
                for (int bn = 0; bn < 4; bn++) {
                    mma_tf32(c[am][bn], ah[am], bh[bn]);
                    mma_tf32(c[am][bn], ah[am], bl[bn]);
                    mma_tf32(c[am][bn], al[am], bh[bn]);
                }
        }
    }

    // ---- epilogue: frags -> smem stage (pre-bias) ----
    __syncthreads();
    float* stage = smf;
#pragma unroll
    for (int am = 0; am < AM; am++) {
        int row0 = wm * (BM / 4) + am * 16 + g;
#pragma unroll
        for (int bn = 0; bn < 4; bn++) {
            int col = wn * 32 + bn * 8 + 2 * tig;
            stage[(row0    ) * SC + col    ] = c[am][bn][0];
            stage[(row0    ) * SC + col + 1] = c[am][bn][1];
            stage[(row0 + 8) * SC + col    ] = c[am][bn][2];
            stage[(row0 + 8) * SC + col + 1] = c[am][bn][3];
        }
    }
    __syncthreads();

    if (SUMS && t < 64) {
        float s = 0.f, q = 0.f;
#pragma unroll 8
        for (int r = 0; r < BM; r++) {
            float v = stage[r * SC + t];
            s += v; q += v * v;
        }
        psum[blockIdx.x * 128 + oc0 + t] = s;
        psq [blockIdx.x * 128 + oc0 + t] = q;
    }

#pragma unroll
    for (int i = 0; i < BM / 16; i++) {
        int idx = t + i * 256;
        int row = idx >> 4;
        int cq  = (idx & 15) * 4;
        float4 v = *(float4*)&stage[row * SC + cq];
        if (BIAS) {
            v.x += bias[oc0 + cq + 0];
            v.y += bias[oc0 + cq + 1];
            v.z += bias[oc0 + cq + 2];
            v.w += bias[oc0 + cq + 3];
        }
        *(float4*)(Cout + (size_t)(blockRow + row) * 128 + oc0 + cq) = v;
    }
}

template <int BM>
constexpr int gemm_smem() {
    return (OFF_A + 2 * BM * SA + 2 * 64 * SA) * 4;
}

// ---------------------------------------------------------------------------
// BN finalize (parallel)
// ---------------------------------------------------------------------------
__global__ __launch_bounds__(1024) void bn_finalize(
        const float* __restrict__ psum, const float* __restrict__ psq,
        int nchunks, float invN,
        const float* __restrict__ g, const float* __restrict__ b,
        float* __restrict__ scale, float* __restrict__ shift) {
    __shared__ float ssum[8][128];
    __shared__ float ssq [8][128];
    const int c     = threadIdx.x & 127;
    const int slice = threadIdx.x >> 7;

    float s = 0.f, q = 0.f;
    for (int k = slice; k < nchunks; k += 8) {
        s += psum[k * 128 + c];
        q += psq [k * 128 + c];
    }
    ssum[slice][c] = s;
    ssq [slice][c] = q;
    __syncthreads();

    if (threadIdx.x < 128) {
        float ts = 0.f, tq = 0.f;
#pragma unroll
        for (int y = 0; y < 8; y++) { ts += ssum[y][c]; tq += ssq[y][c]; }
        float mu  = ts * invN;
        float var = fmaxf(tq * invN - mu * mu, 0.f);
        float sc  = g[c] * rsqrtf(var + 1e-5f);
        scale[c] = sc;
        shift[c] = b[c] - mu * sc;
    }
}

// ---------------------------------------------------------------------------
// Launch
// ---------------------------------------------------------------------------
extern "C" void kernel_launch(void* const* d_in, const int* in_sizes, int n_in,
                              void* d_out, int out_size) {
    const float* pts_r1 = (const float*)d_in[0];
    const float* pts_r2 = (const float*)d_in[1];
    const float* pts_r4 = (const float*)d_in[2];
    const float* feat0  = (const float*)d_in[3];
    const float* feat1  = (const float*)d_in[4];
    const float* feat2  = (const float*)d_in[5];
    const float* w3a = (const float*)d_in[6];
    const float* g3  = (const float*)d_in[7];
    const float* b3  = (const float*)d_in[8];
    const float* w3b = (const float*)d_in[9];
    const float* bb3 = (const float*)d_in[10];
    const float* w4a = (const float*)d_in[11];
    const float* g4  = (const float*)d_in[12];
    const float* b4  = (const float*)d_in[13];
    const float* w4b = (const float*)d_in[14];
    const float* bb4 = (const float*)d_in[15];

    const int B  = 2;
    const int N1 = in_sizes[0] / (3 * B);   // 8192
    const int N2 = in_sizes[1] / (3 * B);   // 4096
    const int N4 = in_sizes[2] / (3 * B);   // 2048

    float *f2i, *h3, *n3, *n3i, *h4, *psum, *psq, *scale, *shift;
    cudaGetSymbolAddress((void**)&f2i,   g_f2i);
    cudaGetSymbolAddress((void**)&h3,    g_h3);
    cudaGetSymbolAddress((void**)&n3,    g_n3);
    cudaGetSymbolAddress((void**)&n3i,   g_n3i);
    cudaGetSymbolAddress((void**)&h4,    g_h4);
    cudaGetSymbolAddress((void**)&psum,  g_psum);
    cudaGetSymbolAddress((void**)&psq,   g_psq);
    cudaGetSymbolAddress((void**)&scale, g_scale);
    cudaGetSymbolAddress((void**)&shift, g_shift);

    cudaFuncSetAttribute(interp3nn, cudaFuncAttributeMaxDynamicSharedMemorySize,
                         (int)(4096 * sizeof(float4)));
    cudaFuncSetAttribute(gemm_mma<128, 256, true, false, true, false>,
                         cudaFuncAttributeMaxDynamicSharedMemorySize, gemm_smem<128>());
    cudaFuncSetAttribute(gemm_mma<128, 128, false, true, false, true>,
                         cudaFuncAttributeMaxDynamicSharedMemorySize, gemm_smem<128>());

    // --- fnode 3: interp feat2 (r4 grid) onto r2 grid ---
    {
        dim3 grid((N2 + IWARPS * TPW - 1) / (IWARPS * TPW), B);
        size_t shmem = (size_t)N4 * sizeof(float4);
        interp3nn<<<grid, 256, shmem>>>(pts_r4, pts_r2, feat2, f2i, N4, N2);
    }
    // h3 = concat(feat1, f2i) @ w3a^T (+ BN partial sums)   [8192 rows]
    gemm_mma<64, 256, true, false, true, false>
        <<<dim3((B * N2) / 64, 2), 256, gemm_smem<64>()>>>(
        feat1, f2i, w3a, nullptr, nullptr, nullptr, h3, psum, psq);
    bn_finalize<<<1, 1024>>>(psum, psq, (B * N2) / 64, 1.f / (B * N2), g3, b3, scale, shift);
    // n3 = relu(BN(h3)) @ w3b^T + bb3                       [8192 rows]
    gemm_mma<64, 128, false, true, false, true>
        <<<dim3((B * N2) / 64, 2), 256, gemm_smem<64>()>>>(
        h3, nullptr, w3b, scale, shift, bb3, n3, nullptr, nullptr);

    // --- fnode 4: interp n3 (r2 grid) onto r1 grid ---
    {
        dim3 grid((N1 + IWARPS * TPW - 1) / (IWARPS * TPW), B);
        size_t shmem = (size_t)N2 * sizeof(float4);
        interp3nn<<<grid, 256, shmem>>>(pts_r2, pts_r1, n3, n3i, N2, N1);
    }
    // h4 = concat(feat0, n3i) @ w4a^T (+ BN partial sums)   [16384 rows]
    gemm_mma<128, 256, true, false, true, false>
        <<<dim3((B * N1) / 128, 2), 256, gemm_smem<128>()>>>(
        feat0, n3i, w4a, nullptr, nullptr, nullptr, h4, psum, psq);
    bn_finalize<<<1, 1024>>>(psum, psq, (B * N1) / 128, 1.f / (B * N1), g4, b4, scale, shift);
    // out = relu(BN(h4)) @ w4b^T + bb4                      [16384 rows]
    gemm_mma<128, 128, false, true, false, true>
        <<<dim3((B * N1) / 128, 2), 256, gemm_smem<128>()>>>(
        h4, nullptr, w4b, scale, shift, bb4, (float*)d_out, nullptr, nullptr);
}

// round 14
// speedup vs baseline: 1.0581x; 1.0018x over previous
#include <cuda_runtime.h>
#include <cstdint>

// ---------------------------------------------------------------------------
// PointGiraffeLayer: 3-NN interpolate -> FC(BN,ReLU) -> 3-NN interpolate -> FC
// B=2, N1=8192, N2=4096, N4=2048, C=128.
// Interp: EXACT grid-binned 3-NN (counting sort + ring search with coverage
//         guarantee + (d,idx) tiebreak), warp gather epilogue.
// GEMMs: mma.sync m16n8k8 tf32, 3xTF32 compensation, cp.async double buffer.
// ---------------------------------------------------------------------------

#define CCH 128

__device__ float g_f2i[2 * 4096 * CCH];
__device__ float g_h3 [2 * 4096 * CCH];
__device__ float g_n3 [2 * 4096 * CCH];
__device__ float g_n3i[2 * 8192 * CCH];
__device__ float g_h4 [2 * 8192 * CCH];
__device__ float g_psum[512 * 128];
__device__ float g_psq [512 * 128];
__device__ float g_scale[128];
__device__ float g_shift[128];
// binning scratch
__device__ float4 g_bp1[2 * 2048];
__device__ float4 g_bp2[2 * 4096];
__device__ int    g_cs1[2 * (8 * 8 * 8 + 1)];
__device__ int    g_cs2[2 * (10 * 10 * 10 + 1)];

__device__ __forceinline__ uint32_t tf32_rna(float a) {
    uint32_t u;
    asm("cvt.rna.tf32.f32 %0, %1;" : "=r"(u) : "f"(a));
    return u;
}

__device__ __forceinline__ void mma_tf32(float c[4], const uint32_t a[4],
                                         const uint32_t b[2]) {
    asm volatile(
        "mma.sync.aligned.m16n8k8.row.col.f32.tf32.tf32.f32 "
        "{%0,%1,%2,%3}, {%4,%5,%6,%7}, {%8,%9}, {%0,%1,%2,%3};"
        : "+f"(c[0]), "+f"(c[1]), "+f"(c[2]), "+f"(c[3])
        : "r"(a[0]), "r"(a[1]), "r"(a[2]), "r"(a[3]), "r"(b[0]), "r"(b[1]));
}

__device__ __forceinline__ uint32_t smem_u32(const void* p) {
    uint32_t a;
    asm("{ .reg .u64 t; cvta.to.shared.u64 t, %1; cvt.u32.u64 %0, t; }"
        : "=r"(a) : "l"(p));
    return a;
}
__device__ __forceinline__ void cp_async16(uint32_t saddr, const void* g) {
    asm volatile("cp.async.ca.shared.global [%0], [%1], 16;" :: "r"(saddr), "l"(g));
}
__device__ __forceinline__ void cp_commit() {
    asm volatile("cp.async.commit_group;" ::: "memory");
}
template <int N>
__device__ __forceinline__ void cp_wait() {
    asm volatile("cp.async.wait_group %0;" :: "n"(N) : "memory");
}

// ---------------------------------------------------------------------------
// Counting-sort build: one block per batch. smem histogram + scan + scatter.
// ---------------------------------------------------------------------------
template <int NS, int G>
__global__ __launch_bounds__(1024) void build_bins(
        const float* __restrict__ src_xyz,   // (B,NS,3)
        float4* __restrict__ out_pts,        // (B,NS) sorted (x,y,z,idx)
        int* __restrict__ out_start) {       // (B,G^3+1)
    constexpr int G3  = G * G * G;
    constexpr int PPT = NS / 1024;
    __shared__ int cnt[G3];
    __shared__ int ofs[G3];
    __shared__ int wsum[32];

    const int b = blockIdx.x;
    const int t = threadIdx.x;
    const float inv_h = (float)G / 70.0f;

    for (int i = t; i < G3; i += 1024) cnt[i] = 0;
    __syncthreads();

    float px[PPT], py[PPT], pz[PPT];
    int   pc[PPT], pi[PPT];
    const float* S = src_xyz + (size_t)b * NS * 3;
#pragma unroll
    for (int k = 0; k < PPT; k++) {
        int i = t + k * 1024;
        float x = S[3 * i + 0], y = S[3 * i + 1], z = S[3 * i + 2];
        int cx = min(G - 1, max(0, (int)(x * inv_h)));
        int cy = min(G - 1, max(0, (int)(y * inv_h)));
        int cz = min(G - 1, max(0, (int)(z * inv_h)));
        int c = (cz * G + cy) * G + cx;
        px[k] = x; py[k] = y; pz[k] = z; pc[k] = c; pi[k] = i;
        atomicAdd(&cnt[c], 1);
    }
    __syncthreads();

    // block-wide exclusive scan of cnt (G3 <= 1024)
    int v = (t < G3) ? cnt[t] : 0;
    int lane = t & 31, wid = t >> 5;
    int x = v;
#pragma unroll
    for (int o = 1; o < 32; o <<= 1) {
        int y = __shfl_up_sync(0xffffffffu, x, o);
        if (lane >= o) x += y;
    }
    if (lane == 31) wsum[wid] = x;
    __syncthreads();
    if (wid == 0) {
        int y = wsum[lane];
#pragma unroll
        for (int o = 1; o < 32; o <<= 1) {
            int z = __shfl_up_sync(0xffffffffu, y, o);
            if (lane >= o) y += z;
        }
        wsum[lane] = y;
    }
    __syncthreads();
    int inc = x + (wid > 0 ? wsum[wid - 1] : 0);
    int ex  = inc - v;
    if (t < G3) {
        ofs[t] = ex;
        out_start[b * (G3 + 1) + t] = ex;
    }
    if (t == 0) out_start[b * (G3 + 1) + G3] = NS;
    __syncthreads();

#pragma unroll
    for (int k = 0; k < PPT; k++) {
        int pos = atomicAdd(&ofs[pc[k]], 1);
        float4 q;
        q.x = px[k]; q.y = py[k]; q.z = pz[k];
        q.w = __int_as_float(pi[k]);
        out_pts[(size_t)b * NS + pos] = q;
    }
}

// ---------------------------------------------------------------------------
// insertion with (d, idx) lexicographic order (matches stable top_k on ties)
// ---------------------------------------------------------------------------
__device__ __forceinline__ void ins3t(float d, int s,
                                      float& d0, int& i0,
                                      float& d1, int& i1,
                                      float& d2, int& i2) {
    if (d < d2 || (d == d2 && s < i2)) {
        if (d < d1 || (d == d1 && s < i1)) {
            d2 = d1; i2 = i1;
            if (d < d0 || (d == d0 && s < i0)) { d1 = d0; i1 = i0; d0 = d; i0 = s; }
            else                               { d1 = d;  i1 = s; }
        } else { d2 = d; i2 = s; }
    }
}

// ---------------------------------------------------------------------------
// Binned exact 3-NN + interpolate.  Thread-per-target search, then
// warp-per-target coalesced gather.  TPB=128.
// ---------------------------------------------------------------------------
template <int NS, int G, int NTB>   // NTB = targets per batch
__global__ __launch_bounds__(128) void interp_binned(
        const float4* __restrict__ bin_pts,   // (B,NS)
        const int* __restrict__ cell_start,   // (B,G^3+1)
        const float* __restrict__ tgt_xyz,    // (B,NTB,3)
        const float* __restrict__ feats,      // (B*NS,128)
        float* __restrict__ out) {            // (B*NTB,128)
    constexpr int G3  = G * G * G;
    constexpr int TPB = 128;
    extern __shared__ char smc[];
    float4* sp     = (float4*)smc;                 // NS
    int*    sstart = (int*)(sp + NS);              // G3+1
    float*  swt    = (float*)(sstart + G3 + 1);    // TPB*3
    int*    sid    = (int*)(swt + TPB * 3);        // TPB*3

    const int b = blockIdx.y;
    const int t = threadIdx.x;

    for (int i = t; i < NS; i += TPB) sp[i] = bin_pts[(size_t)b * NS + i];
    for (int i = t; i <= G3; i += TPB) sstart[i] = cell_start[b * (G3 + 1) + i];
    __syncthreads();

    const int tgt = blockIdx.x * TPB + t;
    const float* T = tgt_xyz + ((size_t)b * NTB + tgt) * 3;
    const float tx = T[0], ty = T[1], tz = T[2];
    const float h = 70.0f / (float)G;
    const float inv_h = (float)G / 70.0f;
    int cx = min(G - 1, max(0, (int)(tx * inv_h)));
    int cy = min(G - 1, max(0, (int)(ty * inv_h)));
    int cz = min(G - 1, max(0, (int)(tz * inv_h)));

    float d0, d1, d2;
    int   i0, i1, i2;
    for (int R = 1;; R++) {
        d0 = d1 = d2 = 3.4e38f;
        i0 = i1 = i2 = 0x7fffffff;
        int xlo = max(0, cx - R), xhi = min(G - 1, cx + R);
        int ylo = max(0, cy - R), yhi = min(G - 1, cy + R);
        int zlo = max(0, cz - R), zhi = min(G - 1, cz + R);
        for (int z = zlo; z <= zhi; z++) {
            for (int y = ylo; y <= yhi; y++) {
                int base = (z * G + y) * G;
                int s0 = sstart[base + xlo];
                int s1 = sstart[base + xhi + 1];
                for (int p = s0; p < s1; p++) {
                    float4 q = sp[p];
                    float dx = tx - q.x, dy = ty - q.y, dz2 = tz - q.z;
                    float d = dx * dx + dy * dy + dz2 * dz2;
                    ins3t(d, __float_as_int(q.w), d0, i0, d1, i1, d2, i2);
                }
            }
        }
        // coverage guarantee: distance to nearest uncovered block face
        float rs = 3.4e38f;
        if (xlo > 0)     rs = fminf(rs, tx - xlo * h);
        if (xhi < G - 1) rs = fminf(rs, (xhi + 1) * h - tx);
        if (ylo > 0)     rs = fminf(rs, ty - ylo * h);
        if (yhi < G - 1) rs = fminf(rs, (yhi + 1) * h - ty);
        if (zlo > 0)     rs = fminf(rs, tz - zlo * h);
        if (zhi < G - 1) rs = fminf(rs, (zhi + 1) * h - tz);
        bool full = (xlo == 0 && ylo == 0 && zlo == 0 &&
                     xhi == G - 1 && yhi == G - 1 && zhi == G - 1);
        if (full || (rs >= 0.f && d2 <= rs * rs)) break;
    }

    {
        float s0 = sqrtf(fmaxf(d0, 0.f));
        float s1 = sqrtf(fmaxf(d1, 0.f));
        float s2 = sqrtf(fmaxf(d2, 0.f));
        float w0 = 1.f / (s0 + 1e-8f);
        float w1 = 1.f / (s1 + 1e-8f);
        float w2 = 1.f / (s2 + 1e-8f);
        float wi = 1.f / (w0 + w1 + w2);
        swt[t * 3 + 0] = w0 * wi;
        swt[t * 3 + 1] = w1 * wi;
        swt[t * 3 + 2] = w2 * wi;
        sid[t * 3 + 0] = i0;
        sid[t * 3 + 1] = i1;
        sid[t * 3 + 2] = i2;
    }
    __syncthreads();

    // warp-per-target coalesced gather (float4 per lane = 128 channels)
    const int lane = t & 31;
    const int warp = t >> 5;
    for (int j = warp; j < TPB; j += TPB / 32) {
        float w0 = swt[j * 3 + 0], w1 = swt[j * 3 + 1], w2 = swt[j * 3 + 2];
        const float4* f0 = (const float4*)(feats + ((size_t)b * NS + sid[j * 3 + 0]) * CCH);
        const float4* f1 = (const float4*)(feats + ((size_t)b * NS + sid[j * 3 + 1]) * CCH);
        const float4* f2 = (const float4*)(feats + ((size_t)b * NS + sid[j * 3 + 2]) * CCH);
        float4 a = f0[lane], bb = f1[lane], cc = f2[lane];
        float4 r;
        r.x = w0 * a.x + w1 * bb.x + w2 * cc.x;
        r.y = w0 * a.y + w1 * bb.y + w2 * cc.y;
        r.z = w0 * a.z + w1 * bb.z + w2 * cc.z;
        r.w = w0 * a.w + w1 * bb.w + w2 * cc.w;
        int gt = blockIdx.x * TPB + j;
        ((float4*)(out + ((size_t)b * NTB + gt) * CCH))[lane] = r;
    }
}

// ---------------------------------------------------------------------------
// mma.sync tf32 GEMM, cp.async double-buffered, register-side 3xTF32 split.
// C (rows x 128) = X (rows x KD) @ W^T.  CTA tile BM(M) x 64(N) x 32(K).
// 256 threads = 8 warps (4m x 2n); warp tile (BM/4) x 32. grid=(rows/BM, 2).
// ---------------------------------------------------------------------------
constexpr int SA = 36;
constexpr int SC = 68;
constexpr int OFF_SCL = 0;
constexpr int OFF_A   = 256;

template <int BM, int KD, bool SPLIT, bool AFFINE, bool SUMS, bool BIAS>
__global__ __launch_bounds__(256) void gemm_mma(
        const float* __restrict__ A0, const float* __restrict__ A1,
        const float* __restrict__ W,
        const float* __restrict__ scale, const float* __restrict__ shift,
        const float* __restrict__ bias,
        float* __restrict__ Cout,
        float* __restrict__ psum, float* __restrict__ psq) {
    constexpr int AM      = BM / 64;
    constexpr int A_WORDS = BM * SA;
    constexpr int B_WORDS = 64 * SA;
    constexpr int OFF_B   = OFF_A + 2 * A_WORDS;

    extern __shared__ float smf[];
    const uint32_t smb = smem_u32(smf);

    const int t    = threadIdx.x;
    const int lane = t & 31;
    const int warp = t >> 5;
    const int wm   = warp >> 1;
    const int wn   = warp & 1;
    const int g    = lane >> 2;
    const int tig  = lane & 3;
    const int blockRow = blockIdx.x * BM;
    const int oc0      = blockIdx.y * 64;

    if (AFFINE) {
        if (t < 128) {
            smf[OFF_SCL + t]       = scale[t];
            smf[OFF_SCL + 128 + t] = shift[t];
        }
    }

    const int arow = t >> 3;
    const int acq  = (t & 7) * 4;

    auto prefetch = [&](int kc) {
        int buf = kc & 1;
        uint32_t abase = smb + (OFF_A + buf * A_WORDS) * 4;
#pragma unroll
        for (int i = 0; i < BM / 32; i++) {
            int row = arow + i * 32;
            int kg  = kc * 32 + acq;
            const float* src;
            if (SPLIT) {
                src = (kg < 128) ? A0 + (size_t)(blockRow + row) * 128 + kg
                                 : A1 + (size_t)(blockRow + row) * 128 + (kg - 128);
            } else {
                src = A0 + (size_t)(blockRow + row) * KD + kg;
            }
            cp_async16(abase + (row * SA + acq) * 4, src);
        }
        uint32_t bbase = smb + (OFF_B + buf * B_WORDS) * 4;
#pragma unroll
        for (int i = 0; i < 2; i++) {
            int row = arow + i * 32;
            const float* src = W + (size_t)(oc0 + row) * KD + kc * 32 + acq;
            cp_async16(bbase + (row * SA + acq) * 4, src);
        }
        cp_commit();
    };

    float c[AM][4][4];
#pragma unroll
    for (int am = 0; am < AM; am++)
#pragma unroll
        for (int bn = 0; bn < 4; bn++)
#pragma unroll
            for (int r = 0; r < 4; r++) c[am][bn][r] = 0.f;

    constexpr int CH = KD / 32;
    prefetch(0);

#pragma unroll
    for (int kc = 0; kc < CH; kc++) {
        __syncthreads();
        if (kc + 1 < CH) {
            prefetch(kc + 1);
            cp_wait<1>();
        } else {
            cp_wait<0>();
        }
        __syncthreads();

        const float* Ab = smf + OFF_A + (kc & 1) * A_WORDS;
        const float* Bb = smf + OFF_B + (kc & 1) * B_WORDS;

#pragma unroll
        for (int ks = 0; ks < 4; ks++) {
            const int k0 = ks * 8;
            float sc0 = 1.f, sh0 = 0.f, sc1 = 1.f, sh1 = 0.f;
            if (AFFINE) {
                int kg = kc * 32 + k0 + tig;
                sc0 = smf[OFF_SCL + kg];
                sh0 = smf[OFF_SCL + 128 + kg];
                sc1 = smf[OFF_SCL + kg + 4];
                sh1 = smf[OFF_SCL + 128 + kg + 4];
            }
            uint32_t ah[AM][4], al[AM][4];
#pragma unroll
            for (int am = 0; am < AM; am++) {
                int r = wm * (BM / 4) + am * 16 + g;
                float v0 = Ab[(r    ) * SA + k0 + tig];
                float v1 = Ab[(r + 8) * SA + k0 + tig];
                float v2 = Ab[(r    ) * SA + k0 + tig + 4];
                float v3 = Ab[(r + 8) * SA + k0 + tig + 4];
                if (AFFINE) {
                    v0 = fmaxf(v0 * sc0 + sh0, 0.f);
                    v1 = fmaxf(v1 * sc0 + sh0, 0.f);
                    v2 = fmaxf(v2 * sc1 + sh1, 0.f);
                    v3 = fmaxf(v3 * sc1 + sh1, 0.f);
                }
                ah[am][0] = tf32_rna(v0); al[am][0] = __float_as_uint(v0 - __uint_as_float(ah[am][0]));
                ah[am][1] = tf32_rna(v1); al[am][1] = __float_as_uint(v1 - __uint_as_float(ah[am][1]));
                ah[am][2] = tf32_rna(v2); al[am][2] = __float_as_uint(v2 - __uint_as_float(ah[am][2]));
                ah[am][3] = tf32_rna(v3); al[am][3] = __float_as_uint(v3 - __uint_as_float(ah[am][3]));
            }
            uint32_t bh[4][2], bl[4][2];
#pragma unroll
            for (int bn = 0; bn < 4; bn++) {
                int n = wn * 32 + bn * 8 + g;
                float w0 = Bb[n * SA + k0 + tig];
                float w1 = Bb[n * SA + k0 + tig + 4];
                bh[bn][0] = tf32_rna(w0); bl[bn][0] = __float_as_uint(w0 - __uint_as_float(bh[bn][0]));
                bh[bn][1] = tf32_rna(w1); bl[bn][1] = __float_as_uint(w1 - __uint_as_float(bh[bn][1]));
            }
#pragma unroll
            for (int am = 0; am < AM; am++)
#pragma unroll
                for (int bn = 0; bn < 4; bn++) {
                    mma_tf32(c[am][bn], ah[am], bh[bn]);
                    mma_tf32(c[am][bn], ah[am], bl[bn]);
                    mma_tf32(c[am][bn], al[am], bh[bn]);
                }
        }
    }

    // ---- epilogue: frags -> smem stage (pre-bias) ----
    __syncthreads();
    float* stage = smf;
#pragma unroll
    for (int am = 0; am < AM; am++) {
        int row0 = wm * (BM / 4) + am * 16 + g;
#pragma unroll
        for (int bn = 0; bn < 4; bn++) {
            int col = wn * 32 + bn * 8 + 2 * tig;
            stage[(row0    ) * SC + col    ] = c[am][bn][0];
            stage[(row0    ) * SC + col + 1] = c[am][bn][1];
            stage[(row0 + 8) * SC + col    ] = c[am][bn][2];
            stage[(row0 + 8) * SC + col + 1] = c[am][bn][3];
        }
    }
    __syncthreads();

    if (SUMS && t < 64) {
        float s = 0.f, q = 0.f;
#pragma unroll 8
        for (int r = 0; r < BM; r++) {
            float v = stage[r * SC + t];
            s += v; q += v * v;
        }
        psum[blockIdx.x * 128 + oc0 + t] = s;
        psq [blockIdx.x * 128 + oc0 + t] = q;
    }

#pragma unroll
    for (int i = 0; i < BM / 16; i++) {
        int idx = t + i * 256;
        int row = idx >> 4;
        int cq  = (idx & 15) * 4;
        float4 v = *(float4*)&stage[row * SC + cq];
        if (BIAS) {
            v.x += bias[oc0 + cq + 0];
            v.y += bias[oc0 + cq + 1];
            v.z += bias[oc0 + cq + 2];
            v.w += bias[oc0 + cq + 3];
        }
        *(float4*)(Cout + (size_t)(blockRow + row) * 128 + oc0 + cq) = v;
    }
}

template <int BM>
constexpr int gemm_smem() {
    return (OFF_A + 2 * BM * SA + 2 * 64 * SA) * 4;
}

// ---------------------------------------------------------------------------
// BN finalize (parallel)
// ---------------------------------------------------------------------------
__global__ __launch_bounds__(1024) void bn_finalize(
        const float* __restrict__ psum, const float* __restrict__ psq,
        int nchunks, float invN,
        const float* __restrict__ g, const float* __restrict__ b,
        float* __restrict__ scale, float* __restrict__ shift) {
    __shared__ float ssum[8][128];
    __shared__ float ssq [8][128];
    const int c     = threadIdx.x & 127;
    const int slice = threadIdx.x >> 7;

    float s = 0.f, q = 0.f;
    for (int k = slice; k < nchunks; k += 8) {
        s += psum[k * 128 + c];
        q += psq [k * 128 + c];
    }
    ssum[slice][c] = s;
    ssq [slice][c] = q;
    __syncthreads();

    if (threadIdx.x < 128) {
        float ts = 0.f, tq = 0.f;
#pragma unroll
        for (int y = 0; y < 8; y++) { ts += ssum[y][c]; tq += ssq[y][c]; }
        float mu  = ts * invN;
        float var = fmaxf(tq * invN - mu * mu, 0.f);
        float sc  = g[c] * rsqrtf(var + 1e-5f);
        scale[c] = sc;
        shift[c] = b[c] - mu * sc;
    }
}

// ---------------------------------------------------------------------------
// Launch
// ---------------------------------------------------------------------------
extern "C" void kernel_launch(void* const* d_in, const int* in_sizes, int n_in,
                              void* d_out, int out_size) {
    const float* pts_r1 = (const float*)d_in[0];
    const float* pts_r2 = (const float*)d_in[1];
    const float* pts_r4 = (const float*)d_in[2];
    const float* feat0  = (const float*)d_in[3];
    const float* feat1  = (const float*)d_in[4];
    const float* feat2  = (const float*)d_in[5];
    const float* w3a = (const float*)d_in[6];
    const float* g3  = (const float*)d_in[7];
    const float* b3  = (const float*)d_in[8];
    const float* w3b = (const float*)d_in[9];
    const float* bb3 = (const float*)d_in[10];
    const float* w4a = (const float*)d_in[11];
    const float* g4  = (const float*)d_in[12];
    const float* b4  = (const float*)d_in[13];
    const float* w4b = (const float*)d_in[14];
    const float* bb4 = (const float*)d_in[15];

    const int B  = 2;
    const int N1 = in_sizes[0] / (3 * B);   // 8192
    const int N2 = in_sizes[1] / (3 * B);   // 4096

    float *f2i, *h3, *n3, *n3i, *h4, *psum, *psq, *scale, *shift;
    float4 *bp1, *bp2; int *cs1, *cs2;
    cudaGetSymbolAddress((void**)&f2i,   g_f2i);
    cudaGetSymbolAddress((void**)&h3,    g_h3);
    cudaGetSymbolAddress((void**)&n3,    g_n3);
    cudaGetSymbolAddress((void**)&n3i,   g_n3i);
    cudaGetSymbolAddress((void**)&h4,    g_h4);
    cudaGetSymbolAddress((void**)&psum,  g_psum);
    cudaGetSymbolAddress((void**)&psq,   g_psq);
    cudaGetSymbolAddress((void**)&scale, g_scale);
    cudaGetSymbolAddress((void**)&shift, g_shift);
    cudaGetSymbolAddress((void**)&bp1,   g_bp1);
    cudaGetSymbolAddress((void**)&bp2,   g_bp2);
    cudaGetSymbolAddress((void**)&cs1,   g_cs1);
    cudaGetSymbolAddress((void**)&cs2,   g_cs2);

    // smem sizes for binned interp
    const int SM1 = 2048 * 16 + (8 * 8 * 8 + 1) * 4 + 128 * 3 * 4 * 2;       // ~37.9KB
    const int SM2 = 4096 * 16 + (10 * 10 * 10 + 1) * 4 + 128 * 3 * 4 * 2;    // ~72.6KB
    cudaFuncSetAttribute(interp_binned<2048, 8, 4096>,
                         cudaFuncAttributeMaxDynamicSharedMemorySize, SM1);
    cudaFuncSetAttribute(interp_binned<4096, 10, 8192>,
                         cudaFuncAttributeMaxDynamicSharedMemorySize, SM2);
    // CRITICAL: BM=128 GEMM needs >48KB dynamic smem opt-in (56320 B).
    cudaFuncSetAttribute(gemm_mma<128, 256, true, false, true, false>,
                         cudaFuncAttributeMaxDynamicSharedMemorySize, gemm_smem<128>());
    cudaFuncSetAttribute(gemm_mma<128, 128, false, true, false, true>,
                         cudaFuncAttributeMaxDynamicSharedMemorySize, gemm_smem<128>());

    // --- fnode 3: binned interp feat2 (r4 grid) onto r2 grid ---
    build_bins<2048, 8><<<2, 1024>>>(pts_r4, bp1, cs1);
    interp_binned<2048, 8, 4096><<<dim3(N2 / 128, B), 128, SM1>>>(
        bp1, cs1, pts_r2, feat2, f2i);

    // h3 = concat(feat1, f2i) @ w3a^T (+ BN partial sums)   [8192 rows]
    gemm_mma<64, 256, true, false, true, false>
        <<<dim3((B * N2) / 64, 2), 256, gemm_smem<64>()>>>(
        feat1, f2i, w3a, nullptr, nullptr, nullptr, h3, psum, psq);
    bn_finalize<<<1, 1024>>>(psum, psq, (B * N2) / 64, 1.f / (B * N2), g3, b3, scale, shift);
    gemm_mma<64, 128, false, true, false, true>
        <<<dim3((B * N2) / 64, 2), 256, gemm_smem<64>()>>>(
        h3, nullptr, w3b, scale, shift, bb3, n3, nullptr, nullptr);

    // --- fnode 4: binned interp n3 (r2 grid) onto r1 grid ---
    build_bins<4096, 10><<<2, 1024>>>(pts_r2, bp2, cs2);
    interp_binned<4096, 10, 8192><<<dim3(N1 / 128, B), 128, SM2>>>(
        bp2, cs2, pts_r1, n3, n3i);

    // h4 = concat(feat0, n3i) @ w4a^T (+ BN partial sums)   [16384 rows]
    gemm_mma<128, 256, true, false, true, false>
        <<<dim3((B * N1) / 128, 2), 256, gemm_smem<128>()>>>(
        feat0, n3i, w4a, nullptr, nullptr, nullptr, h4, psum, psq);
    bn_finalize<<<1, 1024>>>(psum, psq, (B * N1) / 128, 1.f / (B * N1), g4, b4, scale, shift);
    gemm_mma<128, 128, false, true, false, true>
        <<<dim3((B * N1) / 128, 2), 256, gemm_smem<128>()>>>(
        h4, nullptr, w4b, scale, shift, bb4, (float*)d_out, nullptr, nullptr);
}